// round 5
// baseline (speedup 1.0000x reference)
#include <cuda_runtime.h>
#include <math.h>

#define GN 3136          // H*W
#define CC 384
#define BB 8
#define NHEADS 8
#define HD 48
#define SZ (BB*CC*GN)    // 9,633,792

typedef unsigned long long ull;

// ---------------- scratch (static device globals; no runtime alloc) ----------------
__device__ __align__(16) float g_bufA[SZ];
__device__ __align__(16) float g_bufB[SZ];
__device__ __align__(16) float g_x1b[SZ];
__device__ __align__(16) float g_x2b[SZ];
__device__ __align__(16) float g_qkvb[3*SZ];
__device__ __align__(16) float g_hmid[4*SZ];
__device__ __align__(16) float g_w1f[CC*CC];
__device__ __align__(16) float g_b1f[CC];
__device__ __align__(16) float g_dwf[CC*9];
__device__ __align__(16) float g_dbf[CC];
__device__ __align__(16) float g_w1t[CC*4*CC];
__device__ __align__(16) float g_w2t[CC*4*CC];
__device__ __align__(16) float g_kv[BB*NHEADS*HD*HD];
__device__ __align__(16) float g_ksum[BB*NHEADS*HD];

// ---------------- BN folding ----------------
__global__ void fold_bn1_kernel(const float* __restrict__ cw1, const float* __restrict__ cb1,
                                const float* __restrict__ w, const float* __restrict__ bvec,
                                const float* __restrict__ m, const float* __restrict__ v) {
    int o = blockIdx.x;
    int tid = threadIdx.x;   // 128
    float part = 0.f;
    for (int i = tid; i < CC; i += 128) {
        float s = w[i] * rsqrtf(v[i] + 1e-5f);
        float t = bvec[i] - m[i] * s;
        float cv = cw1[o*CC + i];
        g_w1f[o*CC + i] = cv * s;
        part += cv * t;
    }
    __shared__ float red[128];
    red[tid] = part; __syncthreads();
    for (int st = 64; st > 0; st >>= 1) { if (tid < st) red[tid] += red[tid+st]; __syncthreads(); }
    if (tid == 0) g_b1f[o] = cb1[o] + red[0];
}

__global__ void fold_bn2_kernel(const float* __restrict__ dw, const float* __restrict__ db,
                                const float* __restrict__ w, const float* __restrict__ bvec,
                                const float* __restrict__ m, const float* __restrict__ v) {
    int c = blockIdx.x * blockDim.x + threadIdx.x;
    if (c < CC) {
        float s = w[c] * rsqrtf(v[c] + 1e-5f);
        float t = bvec[c] - m[c] * s;
        #pragma unroll
        for (int k = 0; k < 9; k++) g_dwf[c*9 + k] = dw[c*9 + k] * s;
        g_dbf[c] = db[c] * s + t;
    }
}

__global__ void transpose_kernel(const float* __restrict__ src, float* __restrict__ dst,
                                 int srows, int scols) {
    int idx = blockIdx.x * 256 + threadIdx.x;
    if (idx < srows * scols) {
        int a = idx / srows;
        int b = idx - a * srows;
        dst[idx] = src[b * scols + a];
    }
}

__global__ void zero_kv_kernel() {
    int i = blockIdx.x * 256 + threadIdx.x;
    if (i < BB*NHEADS*HD*HD) g_kv[i] = 0.f;
    if (i < BB*NHEADS*HD)    g_ksum[i] = 0.f;
}

// ---------------- fp32 GEMM with packed f32x2 FMA ----------------
// Y[b,o,n] = act(W[o,:]·X[b,:,n] + bias[o]) (+ res)
// W: (Cout x K) row-major; X,Y,res per-batch (chan x GN).
// BM=128, BN=64, BK=16, 128 threads, 8x8 microtile, fma.rn.f32x2.
template<int ACT>
__global__ __launch_bounds__(128)
void gemm2_kernel(const float* __restrict__ W, const float* __restrict__ X,
                  const float* __restrict__ bias, const float* __restrict__ res,
                  float* __restrict__ Y, int Cout, int K) {
    const int b  = blockIdx.z;
    const int m0 = blockIdx.y * 128;
    const int n0 = blockIdx.x * 64;
    const float* Xb = X + (size_t)b * K * GN;
    float* Yb = Y + (size_t)b * Cout * GN;
    const float* Rb = res ? res + (size_t)b * Cout * GN : nullptr;

    __shared__ float As[16][128];   // [k][m]
    __shared__ float Bs[16][64];    // [k][n]

    const int tid = threadIdx.x;     // 128
    const int tm = tid >> 3;         // 0..15 -> 8 rows (m)
    const int tn = tid & 7;          // 0..7  -> 8 cols (n)

    ull acc[8][4];                   // 8 rows x 4 col-pairs
    #pragma unroll
    for (int i = 0; i < 8; i++)
        #pragma unroll
        for (int j = 0; j < 4; j++) acc[i][j] = 0ULL;

    // staging registers for software-pipelined global loads
    float4 aR[4];   // thread owns A row (m0+tid), k chunk of 16
    float4 bR[2];   // B tile 16x64 = 256 float4; thread -> idx 2*tid, 2*tid+1

    const float* Wrow = W + (size_t)(m0 + tid) * K;
    {
        #pragma unroll
        for (int c = 0; c < 4; c++)
            aR[c] = *reinterpret_cast<const float4*>(&Wrow[c*4]);
        #pragma unroll
        for (int h = 0; h < 2; h++) {
            int idx = tid*2 + h; int k = idx >> 4; int n4 = idx & 15;
            bR[h] = *reinterpret_cast<const float4*>(&Xb[(size_t)k * GN + n0 + n4*4]);
        }
    }

    for (int k0 = 0; k0 < K; k0 += 16) {
        // stage -> smem
        #pragma unroll
        for (int c = 0; c < 4; c++) {
            As[c*4+0][tid] = aR[c].x; As[c*4+1][tid] = aR[c].y;
            As[c*4+2][tid] = aR[c].z; As[c*4+3][tid] = aR[c].w;
        }
        #pragma unroll
        for (int h = 0; h < 2; h++) {
            int idx = tid*2 + h; int k = idx >> 4; int n4 = idx & 15;
            *reinterpret_cast<float4*>(&Bs[k][n4*4]) = bR[h];
        }
        __syncthreads();

        // prefetch next tile while computing this one
        if (k0 + 16 < K) {
            #pragma unroll
            for (int c = 0; c < 4; c++)
                aR[c] = *reinterpret_cast<const float4*>(&Wrow[k0 + 16 + c*4]);
            #pragma unroll
            for (int h = 0; h < 2; h++) {
                int idx = tid*2 + h; int k = idx >> 4; int n4 = idx & 15;
                bR[h] = *reinterpret_cast<const float4*>(&Xb[(size_t)(k0 + 16 + k) * GN + n0 + n4*4]);
            }
        }

        #pragma unroll
        for (int kk = 0; kk < 16; kk++) {
            float4 a0 = *reinterpret_cast<float4*>(&As[kk][tm*8]);
            float4 a1 = *reinterpret_cast<float4*>(&As[kk][tm*8 + 4]);
            ulonglong2 bv0 = *reinterpret_cast<ulonglong2*>(&Bs[kk][tn*8]);
            ulonglong2 bv1 = *reinterpret_cast<ulonglong2*>(&Bs[kk][tn*8 + 4]);
            ull bp[4] = {bv0.x, bv0.y, bv1.x, bv1.y};
            float av[8] = {a0.x,a0.y,a0.z,a0.w,a1.x,a1.y,a1.z,a1.w};
            #pragma unroll
            for (int i = 0; i < 8; i++) {
                unsigned au = __float_as_uint(av[i]);
                ull a2;
                asm("mov.b64 %0, {%1,%1};" : "=l"(a2) : "r"(au));
                #pragma unroll
                for (int j = 0; j < 4; j++)
                    asm("fma.rn.f32x2 %0, %1, %2, %0;"
                        : "+l"(acc[i][j]) : "l"(a2), "l"(bp[j]));
            }
        }
        __syncthreads();
    }

    // epilogue
    #pragma unroll
    for (int i = 0; i < 8; i++) {
        int m = m0 + tm*8 + i;
        float bval = bias ? bias[m] : 0.f;
        size_t off = (size_t)m * GN + n0 + tn*8;
        float o[8];
        #pragma unroll
        for (int j = 0; j < 4; j++) {
            unsigned lo, hi;
            asm("mov.b64 {%0,%1}, %2;" : "=r"(lo), "=r"(hi) : "l"(acc[i][j]));
            o[2*j]   = __uint_as_float(lo);
            o[2*j+1] = __uint_as_float(hi);
        }
        float r[8];
        if (Rb) {
            float4 r0 = *reinterpret_cast<const float4*>(&Rb[off]);
            float4 r1 = *reinterpret_cast<const float4*>(&Rb[off + 4]);
            r[0]=r0.x; r[1]=r0.y; r[2]=r0.z; r[3]=r0.w;
            r[4]=r1.x; r[5]=r1.y; r[6]=r1.z; r[7]=r1.w;
        }
        #pragma unroll
        for (int j = 0; j < 8; j++) {
            float t = o[j] + bval;
            if (ACT == 1) t = 0.5f * t * (1.f + erff(t * 0.70710678118654752f));
            if (Rb) t += r[j];
            o[j] = t;
        }
        *reinterpret_cast<float4*>(&Yb[off])     = make_float4(o[0], o[1], o[2], o[3]);
        *reinterpret_cast<float4*>(&Yb[off + 4]) = make_float4(o[4], o[5], o[6], o[7]);
    }
}

static void run_gemm(const float* W, const float* X, const float* bias, const float* res,
                     float* Y, int Cout, int K, int act) {
    dim3 g(GN/64, Cout/128, BB), blk(128);
    if (act) gemm2_kernel<1><<<g, blk>>>(W, X, bias, res, Y, Cout, K);
    else     gemm2_kernel<0><<<g, blk>>>(W, X, bias, res, Y, Cout, K);
}

// ---------------- depthwise 3x3 (BN2-folded weights/bias) ----------------
__global__ __launch_bounds__(256)
void dwconv_kernel(const float* __restrict__ in, float* __restrict__ out) {
    int bc = blockIdx.x;          // b*CC + c
    int c  = bc % CC;
    __shared__ float tile[58*58];
    const float* plane = in + (size_t)bc * GN;
    int tid = threadIdx.x;
    for (int idx = tid; idx < 58*58; idx += 256) {
        int ty = idx / 58, tx = idx - ty*58;
        int y = ty - 1, xq = tx - 1;
        float v = 0.f;
        if (y >= 0 && y < 56 && xq >= 0 && xq < 56) v = plane[y*56 + xq];
        tile[idx] = v;
    }
    __syncthreads();
    float w0=g_dwf[c*9+0], w1=g_dwf[c*9+1], w2=g_dwf[c*9+2];
    float w3=g_dwf[c*9+3], w4=g_dwf[c*9+4], w5=g_dwf[c*9+5];
    float w6=g_dwf[c*9+6], w7=g_dwf[c*9+7], w8=g_dwf[c*9+8];
    float bbv = g_dbf[c];
    float* oplane = out + (size_t)bc * GN;
    for (int p = tid; p < GN; p += 256) {
        int y = p / 56, xq = p - y*56;
        const float* t = &tile[y*58 + xq];
        float a = bbv + w0*t[0] + w1*t[1] + w2*t[2]
                      + w3*t[58] + w4*t[59] + w5*t[60]
                      + w6*t[116] + w7*t[117] + w8*t[118];
        oplane[p] = a;
    }
}

// ---------------- linear attention ----------------
__device__ __forceinline__ float phi_f(float t) { return expf(0.5f * (2.f*t - t*t)); }

__global__ __launch_bounds__(256)
void attn_kv_kernel(const float* __restrict__ qkv) {
    int bh = blockIdx.x; int b = bh >> 3, hd = bh & 7;
    int n0 = blockIdx.y * 392;
    __shared__ float kp_s[28*48];
    __shared__ float vv_s[28*48];
    int tid = threadIdx.x;
    int dr[9], er[9];
    #pragma unroll
    for (int r = 0; r < 9; r++) { int de = tid + 256*r; dr[r] = de/48; er[r] = de - dr[r]*48; }
    float acc[9];
    #pragma unroll
    for (int r = 0; r < 9; r++) acc[r] = 0.f;
    float ks = 0.f;
    const float* kbase = qkv + ((size_t)(b*1152 + CC   + hd*HD)) * GN + n0;
    const float* vbase = qkv + ((size_t)(b*1152 + 2*CC + hd*HD)) * GN + n0;
    for (int j0 = 0; j0 < 392; j0 += 28) {
        for (int idx = tid; idx < 48*28; idx += 256) {
            int d = idx / 28, j = idx - d*28;
            float kvl = kbase[(size_t)d*GN + j0 + j];
            kp_s[j*48 + d] = phi_f(kvl);
            vv_s[j*48 + d] = vbase[(size_t)d*GN + j0 + j];
        }
        __syncthreads();
        #pragma unroll 4
        for (int j = 0; j < 28; j++) {
            #pragma unroll
            for (int r = 0; r < 9; r++)
                acc[r] = fmaf(kp_s[j*48 + dr[r]], vv_s[j*48 + er[r]], acc[r]);
        }
        if (tid < 48) {
            float s = 0.f;
            #pragma unroll 4
            for (int j = 0; j < 28; j++) s += kp_s[j*48 + tid];
            ks += s;
        }
        __syncthreads();
    }
    #pragma unroll
    for (int r = 0; r < 9; r++) atomicAdd(&g_kv[bh*2304 + tid + 256*r], acc[r]);
    if (tid < 48) atomicAdd(&g_ksum[bh*48 + tid], ks);
}

__global__ __launch_bounds__(256)
void attn_out_kernel(const float* __restrict__ qkv, float* __restrict__ outp) {
    int bh = blockIdx.x; int b = bh >> 3, hd = bh & 7;
    int n0 = blockIdx.y * 392;
    __shared__ float kv_s[2304];
    __shared__ float ks_s[48];
    __shared__ float qp_s[28*49];
    __shared__ float dinv[28];
    int tid = threadIdx.x;
    for (int i = tid; i < 2304; i += 256) kv_s[i] = g_kv[bh*2304 + i];
    if (tid < 48) ks_s[tid] = g_ksum[bh*48 + tid];
    __syncthreads();
    const float* qbase = qkv + ((size_t)(b*1152 + hd*HD)) * GN + n0;
    float* obase = outp + ((size_t)(b*CC + hd*HD)) * GN + n0;
    for (int j0 = 0; j0 < 392; j0 += 28) {
        for (int idx = tid; idx < 48*28; idx += 256) {
            int d = idx / 28, j = idx - d*28;
            float q = qbase[(size_t)d*GN + j0 + j];
            qp_s[j*49 + d] = phi_f(q);
        }
        __syncthreads();
        if (tid < 28) {
            float s = 0.f;
            #pragma unroll
            for (int d = 0; d < 48; d++) s = fmaf(qp_s[tid*49 + d], ks_s[d], s);
            dinv[tid] = 1.f / (s + 1e-6f);
        }
        __syncthreads();
        for (int idx = tid; idx < 48*28; idx += 256) {
            int e = idx / 28, j = idx - e*28;
            float s = 0.f;
            #pragma unroll
            for (int d = 0; d < 48; d++) s = fmaf(qp_s[j*49 + d], kv_s[d*48 + e], s);
            obase[(size_t)e*GN + j0 + j] = s * dinv[j];
        }
        __syncthreads();
    }
}

// ---------------- LayerNorm over channels ----------------
__global__ __launch_bounds__(256)
void ln_kernel(const float* __restrict__ x2, const float* __restrict__ lw,
               const float* __restrict__ lb, float* __restrict__ xn) {
    int b = blockIdx.y; int n0 = blockIdx.x * 16;
    __shared__ float s[CC*17];
    __shared__ float r1[256], r2[256];
    __shared__ float mu[16], ri[16];
    const float* base = x2 + (size_t)b * CC * GN + n0;
    int tid = threadIdx.x;
    for (int idx = tid; idx < CC*16; idx += 256) {
        int c = idx >> 4, j = idx & 15;
        s[c*17 + j] = base[(size_t)c * GN + j];
    }
    __syncthreads();
    {
        int j = tid & 15, part = tid >> 4;
        float sm = 0.f, sq = 0.f;
        for (int c = part*24; c < part*24 + 24; c++) {
            float v = s[c*17 + j]; sm += v; sq = fmaf(v, v, sq);
        }
        r1[tid] = sm; r2[tid] = sq;
    }
    __syncthreads();
    if (tid < 16) {
        float a = 0.f, q = 0.f;
        #pragma unroll
        for (int p = 0; p < 16; p++) { a += r1[p*16 + tid]; q += r2[p*16 + tid]; }
        float mean = a * (1.f/384.f);
        float var = q * (1.f/384.f) - mean*mean;
        mu[tid] = mean; ri[tid] = rsqrtf(var + 1e-5f);
    }
    __syncthreads();
    float* obase = xn + (size_t)b * CC * GN + n0;
    for (int idx = tid; idx < CC*16; idx += 256) {
        int c = idx >> 4, j = idx & 15;
        obase[(size_t)c * GN + j] = (s[c*17 + j] - mu[j]) * ri[j] * lw[c] + lb[c];
    }
}

// ---------------- launch ----------------
extern "C" void kernel_launch(void* const* d_in, const int* in_sizes, int n_in,
                              void* d_out, int out_size) {
    const float* x      = (const float*)d_in[0];
    const float* bn1_w  = (const float*)d_in[1];
    const float* bn1_b  = (const float*)d_in[2];
    const float* bn1_m  = (const float*)d_in[3];
    const float* bn1_v  = (const float*)d_in[4];
    const float* cw1    = (const float*)d_in[5];
    const float* cb1    = (const float*)d_in[6];
    const float* dw     = (const float*)d_in[7];
    const float* db     = (const float*)d_in[8];
    const float* bn2_w  = (const float*)d_in[9];
    const float* bn2_b  = (const float*)d_in[10];
    const float* bn2_m  = (const float*)d_in[11];
    const float* bn2_v  = (const float*)d_in[12];
    const float* cw2    = (const float*)d_in[13];
    const float* cb2    = (const float*)d_in[14];
    const float* qkv_w  = (const float*)d_in[15];
    const float* proj_w = (const float*)d_in[16];
    const float* proj_b = (const float*)d_in[17];
    const float* ln_w   = (const float*)d_in[18];
    const float* ln_b   = (const float*)d_in[19];
    const float* mlp_w1 = (const float*)d_in[20];
    const float* mlp_b1 = (const float*)d_in[21];
    const float* mlp_w2 = (const float*)d_in[22];
    const float* mlp_b2 = (const float*)d_in[23];

    float *bufA, *bufB, *x1, *x2, *qkvb, *hmid, *w1f, *b1f, *w1t, *w2t;
    cudaGetSymbolAddress((void**)&bufA, g_bufA);
    cudaGetSymbolAddress((void**)&bufB, g_bufB);
    cudaGetSymbolAddress((void**)&x1,   g_x1b);
    cudaGetSymbolAddress((void**)&x2,   g_x2b);
    cudaGetSymbolAddress((void**)&qkvb, g_qkvb);
    cudaGetSymbolAddress((void**)&hmid, g_hmid);
    cudaGetSymbolAddress((void**)&w1f,  g_w1f);
    cudaGetSymbolAddress((void**)&b1f,  g_b1f);
    cudaGetSymbolAddress((void**)&w1t,  g_w1t);
    cudaGetSymbolAddress((void**)&w2t,  g_w2t);

    // weight prep
    fold_bn1_kernel<<<CC, 128>>>(cw1, cb1, bn1_w, bn1_b, bn1_m, bn1_v);
    fold_bn2_kernel<<<2, 192>>>(dw, db, bn2_w, bn2_b, bn2_m, bn2_v);
    transpose_kernel<<<(CC*4*CC + 255)/256, 256>>>(mlp_w1, w1t, CC, 4*CC);    // (384,1536) -> (1536,384)
    transpose_kernel<<<(CC*4*CC + 255)/256, 256>>>(mlp_w2, w2t, 4*CC, CC);    // (1536,384) -> (384,1536)
    zero_kv_kernel<<<(BB*NHEADS*HD*HD + 255)/256, 256>>>();

    // conv path
    run_gemm(w1f, x, b1f, nullptr, bufA, CC, CC, 0);          // h = BN1+1x1
    dwconv_kernel<<<BB*CC, 256>>>(bufA, bufB);                // h2 = dw3x3 + BN2 (folded)
    run_gemm(cw2, bufB, cb2, x, x1, CC, CC, 0);               // x1 = 1x1 + x

    // linear attention
    run_gemm(qkv_w, x1, nullptr, nullptr, qkvb, 3*CC, CC, 0); // qkv
    attn_kv_kernel<<<dim3(BB*NHEADS, 8), 256>>>(qkvb);
    attn_out_kernel<<<dim3(BB*NHEADS, 8), 256>>>(qkvb, bufA); // attn out
    run_gemm(proj_w, bufA, proj_b, x1, x2, CC, CC, 0);        // x2 = proj + x1

    // LN + MLP
    ln_kernel<<<dim3(GN/16, BB), 256>>>(x2, ln_w, ln_b, bufB);          // xn
    run_gemm(w1t, bufB, mlp_b1, nullptr, hmid, 4*CC, CC, 1);            // gelu(fc1)
    run_gemm(w2t, hmid, mlp_b2, x2, (float*)d_out, CC, 4*CC, 0);        // out = x2 + fc2
}

// round 6
// speedup vs baseline: 2.3886x; 2.3886x over previous
#include <cuda_runtime.h>
#include <cuda_bf16.h>
#include <math.h>
#include <stdint.h>

#define GN 3136          // H*W
#define CC 384
#define BB 8
#define NHEADS 8
#define HD 48
#define SZ (BB*CC*GN)    // 9,633,792

typedef __nv_bfloat16 bf16;
typedef __nv_bfloat162 bf162;

// ---------------- scratch (static device globals; no runtime alloc) ----------------
__device__ __align__(16) float g_bufA[SZ];       // conv mid (fp32, dwconv input)
__device__ __align__(16) float g_x1b[SZ];        // x1 fp32
__device__ __align__(16) float g_x2b[SZ];        // x2 fp32
__device__ __align__(16) float g_qkvb[3*SZ];     // qkv fp32
__device__ __align__(16) float g_w1f[CC*CC];
__device__ __align__(16) float g_b1f[CC];
__device__ __align__(16) float g_dwf[CC*9];
__device__ __align__(16) float g_dbf[CC];
__device__ __align__(16) float g_w1t[CC*4*CC];
__device__ __align__(16) float g_w2t[CC*4*CC];
__device__ __align__(16) float g_kv[BB*NHEADS*HD*HD];
__device__ __align__(16) float g_ksum[BB*NHEADS*HD];

// bf16 hi/lo activation buffers
__device__ __align__(16) bf16 g_xh[SZ],   g_xl[SZ];
__device__ __align__(16) bf16 g_dwh[SZ],  g_dwl[SZ];
__device__ __align__(16) bf16 g_x1h[SZ],  g_x1l[SZ];
__device__ __align__(16) bf16 g_aoh[SZ],  g_aol[SZ];
__device__ __align__(16) bf16 g_lnh[SZ],  g_lnl[SZ];
__device__ __align__(16) bf16 g_hmh[4*SZ], g_hml[4*SZ];
// bf16 hi/lo weights
__device__ __align__(16) bf16 g_w1fh[CC*CC],   g_w1fl[CC*CC];
__device__ __align__(16) bf16 g_cw2h[CC*CC],   g_cw2l[CC*CC];
__device__ __align__(16) bf16 g_qkvh[3*CC*CC], g_qkvl[3*CC*CC];
__device__ __align__(16) bf16 g_projh[CC*CC],  g_projl[CC*CC];
__device__ __align__(16) bf16 g_w1th[CC*4*CC], g_w1tl[CC*4*CC];
__device__ __align__(16) bf16 g_w2th[CC*4*CC], g_w2tl[CC*4*CC];

// ---------------- helpers ----------------
__device__ __forceinline__ void split2(float x, bf16& h, bf16& l) {
    h = __float2bfloat16(x);
    l = __float2bfloat16(x - __bfloat162float(h));
}

__device__ __forceinline__ void ldsm4(uint32_t* r, uint32_t a) {
    asm volatile("ldmatrix.sync.aligned.m8n8.x4.shared.b16 {%0,%1,%2,%3}, [%4];"
                 : "=r"(r[0]), "=r"(r[1]), "=r"(r[2]), "=r"(r[3]) : "r"(a));
}
__device__ __forceinline__ void ldsm4t(uint32_t* r, uint32_t a) {
    asm volatile("ldmatrix.sync.aligned.m8n8.x4.trans.shared.b16 {%0,%1,%2,%3}, [%4];"
                 : "=r"(r[0]), "=r"(r[1]), "=r"(r[2]), "=r"(r[3]) : "r"(a));
}
__device__ __forceinline__ void mma16816(float* c, const uint32_t* a, const uint32_t* b) {
    asm volatile("mma.sync.aligned.m16n8k16.row.col.f32.bf16.bf16.f32 "
                 "{%0,%1,%2,%3}, {%4,%5,%6,%7}, {%8,%9}, {%0,%1,%2,%3};"
                 : "+f"(c[0]), "+f"(c[1]), "+f"(c[2]), "+f"(c[3])
                 : "r"(a[0]), "r"(a[1]), "r"(a[2]), "r"(a[3]), "r"(b[0]), "r"(b[1]));
}
__device__ __forceinline__ void cpa16(uint32_t dst, const void* src) {
    asm volatile("cp.async.ca.shared.global [%0], [%1], 16;" :: "r"(dst), "l"(src));
}

// ---------------- BN folding ----------------
__global__ void fold_bn1_kernel(const float* __restrict__ cw1, const float* __restrict__ cb1,
                                const float* __restrict__ w, const float* __restrict__ bvec,
                                const float* __restrict__ m, const float* __restrict__ v) {
    int o = blockIdx.x;
    int tid = threadIdx.x;   // 128
    float part = 0.f;
    for (int i = tid; i < CC; i += 128) {
        float s = w[i] * rsqrtf(v[i] + 1e-5f);
        float t = bvec[i] - m[i] * s;
        float cv = cw1[o*CC + i];
        g_w1f[o*CC + i] = cv * s;
        part += cv * t;
    }
    __shared__ float red[128];
    red[tid] = part; __syncthreads();
    for (int st = 64; st > 0; st >>= 1) { if (tid < st) red[tid] += red[tid+st]; __syncthreads(); }
    if (tid == 0) g_b1f[o] = cb1[o] + red[0];
}

__global__ void fold_bn2_kernel(const float* __restrict__ dw, const float* __restrict__ db,
                                const float* __restrict__ w, const float* __restrict__ bvec,
                                const float* __restrict__ m, const float* __restrict__ v) {
    int c = blockIdx.x * blockDim.x + threadIdx.x;
    if (c < CC) {
        float s = w[c] * rsqrtf(v[c] + 1e-5f);
        float t = bvec[c] - m[c] * s;
        #pragma unroll
        for (int k = 0; k < 9; k++) g_dwf[c*9 + k] = dw[c*9 + k] * s;
        g_dbf[c] = db[c] * s + t;
    }
}

__global__ void transpose_kernel(const float* __restrict__ src, float* __restrict__ dst,
                                 int srows, int scols) {
    int idx = blockIdx.x * 256 + threadIdx.x;
    if (idx < srows * scols) {
        int a = idx / srows;
        int b = idx - a * srows;
        dst[idx] = src[b * scols + a];
    }
}

__global__ void split_kernel(const float* __restrict__ src, bf16* __restrict__ h,
                             bf16* __restrict__ l, int n) {
    int i = blockIdx.x * 256 + threadIdx.x;
    if (i < n) {
        bf16 hh, ll;
        split2(src[i], hh, ll);
        h[i] = hh; l[i] = ll;
    }
}

__global__ void zero_kv_kernel() {
    int i = blockIdx.x * 256 + threadIdx.x;
    if (i < BB*NHEADS*HD*HD) g_kv[i] = 0.f;
    if (i < BB*NHEADS*HD)    g_ksum[i] = 0.f;
}

// ---------------- bf16 split GEMM (tensor core) ----------------
// Y[b,o,n] = act(W[o,:]·X[b,:,n] + bias[o]) (+ res), W = Wh+Wl, X = Xh+Xl (bf16 split)
// W*: (Cout x K) row-major bf16. X*: per-batch (K x GN) bf16. Outputs fp32 and/or bf16 hi/lo.
// BM=128, BN=64, BK=32, 128 threads, 4 warps (2m x 2n), warp tile 64x32.
// smem per buffer: A (hi|lo interleaved per row, 128 rows x 128B = 16KB), Bh 4KB, Bl 4KB.
#define SM_A    0
#define SM_BH   16384
#define SM_BL   20480
#define SM_BUF  24576

template<int ACT>
__global__ __launch_bounds__(128)
void gemm_bf16(const bf16* __restrict__ Wh, const bf16* __restrict__ Wl,
               const bf16* __restrict__ Xh, const bf16* __restrict__ Xl,
               const float* __restrict__ bias, const float* __restrict__ res,
               float* __restrict__ YF, bf16* __restrict__ YH, bf16* __restrict__ YL,
               int Cout, int K) {
    const int b  = blockIdx.z;
    const int m0 = blockIdx.y * 128;
    const int n0 = blockIdx.x * 64;
    const bf16* Xhb = Xh + (size_t)b * K * GN;
    const bf16* Xlb = Xl + (size_t)b * K * GN;
    const size_t obase = (size_t)b * Cout * GN;

    __shared__ __align__(16) unsigned char smraw[2 * SM_BUF];
    const uint32_t smbase = (uint32_t)__cvta_generic_to_shared(smraw);

    const int tid  = threadIdx.x;
    const int lane = tid & 31;
    const int wid  = tid >> 5;
    const int warp_m = wid & 1;        // 2
    const int warp_n = wid >> 1;       // 2
    const int m_base = warp_m * 64;
    const int n_base = warp_n * 32;

    const int r8   = (lane & 7) + ((lane >> 3) & 1) * 8;  // ldmatrix row-within-16
    const int cadd = lane >> 4;                            // ldmatrix chunk add (0/1)

    float acc[4][4][4];
    #pragma unroll
    for (int i = 0; i < 4; i++)
        #pragma unroll
        for (int nt = 0; nt < 4; nt++)
            #pragma unroll
            for (int q = 0; q < 4; q++) acc[i][nt][q] = 0.f;

    // per-thread copy coords
    const int cpc = tid & 7;           // chunk 0..7
    const int cpm = tid >> 3;          // base row 0..15

    // issue one BK=32 tile into buffer `buf`
    auto issue_tile = [&](int k0, int buf) {
        uint32_t sb = smbase + buf * SM_BUF;
        #pragma unroll
        for (int h = 0; h < 8; h++) {
            int m = cpm + 16*h;                          // 0..127
            uint32_t d = sb + SM_A + m*128 + ((cpc ^ (m & 7)) << 4);
            const bf16* s = (cpc < 4)
                ? (Wh + (size_t)(m0 + m) * K + k0 + cpc*8)
                : (Wl + (size_t)(m0 + m) * K + k0 + (cpc - 4)*8);
            cpa16(d, s);
        }
        #pragma unroll
        for (int h = 0; h < 4; h++) {
            int k = cpm + 16*(h & 1);                    // 0..31
            bool hi = (h < 2);
            uint32_t d = sb + (hi ? SM_BH : SM_BL) + k*128 + ((cpc ^ (k & 7)) << 4);
            const bf16* s = (hi ? Xhb : Xlb) + (size_t)(k0 + k) * GN + n0 + cpc*8;
            cpa16(d, s);
        }
        asm volatile("cp.async.commit_group;" ::: "memory");
    };

    issue_tile(0, 0);
    int cur = 0;
    for (int k0 = 0; k0 < K; k0 += 32) {
        asm volatile("cp.async.wait_group 0;" ::: "memory");
        __syncthreads();
        if (k0 + 32 < K) issue_tile(k0 + 32, cur ^ 1);
        uint32_t sb = smbase + cur * SM_BUF;

        #pragma unroll
        for (int j = 0; j < 2; j++) {                    // two k16 steps
            uint32_t ah[4][4], al[4][4], bh[4][2], bl[4][2];
            #pragma unroll
            for (int i = 0; i < 4; i++) {
                int row = m_base + 16*i + r8;
                int ch = 2*j + cadd;                     // hi chunks 0..3
                ldsm4(ah[i], sb + SM_A + row*128 + (((ch) ^ (row & 7)) << 4));
                int cl = 4 + 2*j + cadd;                 // lo chunks 4..7
                ldsm4(al[i], sb + SM_A + row*128 + (((cl) ^ (row & 7)) << 4));
            }
            #pragma unroll
            for (int u = 0; u < 2; u++) {
                int rowk = 16*j + r8;
                int nc = warp_n*4 + 2*u + cadd;
                uint32_t t[4];
                ldsm4t(t, sb + SM_BH + rowk*128 + ((nc ^ (rowk & 7)) << 4));
                bh[2*u][0] = t[0]; bh[2*u][1] = t[1];
                bh[2*u+1][0] = t[2]; bh[2*u+1][1] = t[3];
                ldsm4t(t, sb + SM_BL + rowk*128 + ((nc ^ (rowk & 7)) << 4));
                bl[2*u][0] = t[0]; bl[2*u][1] = t[1];
                bl[2*u+1][0] = t[2]; bl[2*u+1][1] = t[3];
            }
            #pragma unroll
            for (int i = 0; i < 4; i++)
                #pragma unroll
                for (int nt = 0; nt < 4; nt++) {
                    mma16816(acc[i][nt], ah[i], bh[nt]);
                    mma16816(acc[i][nt], ah[i], bl[nt]);
                    mma16816(acc[i][nt], al[i], bh[nt]);
                }
        }
        cur ^= 1;
    }

    // epilogue
    const int g = lane >> 2, tc = lane & 3;
    #pragma unroll
    for (int i = 0; i < 4; i++) {
        #pragma unroll
        for (int half = 0; half < 2; half++) {
            int row = m0 + m_base + 16*i + g + 8*half;
            float bv = bias ? bias[row] : 0.f;
            size_t rowoff = obase + (size_t)row * GN;
            #pragma unroll
            for (int nt = 0; nt < 4; nt++) {
                int n = n0 + n_base + 8*nt + tc*2;
                float v0 = acc[i][nt][2*half + 0] + bv;
                float v1 = acc[i][nt][2*half + 1] + bv;
                if (ACT == 1) {
                    v0 = 0.5f * v0 * (1.f + erff(v0 * 0.70710678118654752f));
                    v1 = 0.5f * v1 * (1.f + erff(v1 * 0.70710678118654752f));
                }
                if (res) {
                    float2 r = *reinterpret_cast<const float2*>(res + rowoff + n);
                    v0 += r.x; v1 += r.y;
                }
                if (YF) *reinterpret_cast<float2*>(YF + rowoff + n) = make_float2(v0, v1);
                if (YH) {
                    bf16 h0, l0, h1, l1;
                    split2(v0, h0, l0); split2(v1, h1, l1);
                    *reinterpret_cast<bf162*>(YH + rowoff + n) = __halves2bfloat162(h0, h1);
                    *reinterpret_cast<bf162*>(YL + rowoff + n) = __halves2bfloat162(l0, l1);
                }
            }
        }
    }
}

static void run_gemm(const bf16* Wh, const bf16* Wl, const bf16* Xh, const bf16* Xl,
                     const float* bias, const float* res,
                     float* YF, bf16* YH, bf16* YL, int Cout, int K, int act) {
    dim3 g(GN/64, Cout/128, BB), blk(128);
    if (act) gemm_bf16<1><<<g, blk>>>(Wh, Wl, Xh, Xl, bias, res, YF, YH, YL, Cout, K);
    else     gemm_bf16<0><<<g, blk>>>(Wh, Wl, Xh, Xl, bias, res, YF, YH, YL, Cout, K);
}

// ---------------- depthwise 3x3 (BN2-folded), writes bf16 hi/lo ----------------
__global__ __launch_bounds__(256)
void dwconv_kernel(const float* __restrict__ in, bf16* __restrict__ oh, bf16* __restrict__ ol) {
    int bc = blockIdx.x;          // b*CC + c
    int c  = bc % CC;
    __shared__ float tile[58*58];
    const float* plane = in + (size_t)bc * GN;
    int tid = threadIdx.x;
    for (int idx = tid; idx < 58*58; idx += 256) {
        int ty = idx / 58, tx = idx - ty*58;
        int y = ty - 1, xq = tx - 1;
        float v = 0.f;
        if (y >= 0 && y < 56 && xq >= 0 && xq < 56) v = plane[y*56 + xq];
        tile[idx] = v;
    }
    __syncthreads();
    float w0=g_dwf[c*9+0], w1=g_dwf[c*9+1], w2=g_dwf[c*9+2];
    float w3=g_dwf[c*9+3], w4=g_dwf[c*9+4], w5=g_dwf[c*9+5];
    float w6=g_dwf[c*9+6], w7=g_dwf[c*9+7], w8=g_dwf[c*9+8];
    float bbv = g_dbf[c];
    bf16* ohp = oh + (size_t)bc * GN;
    bf16* olp = ol + (size_t)bc * GN;
    for (int p = tid; p < GN; p += 256) {
        int y = p / 56, xq = p - y*56;
        const float* t = &tile[y*58 + xq];
        float a = bbv + w0*t[0] + w1*t[1] + w2*t[2]
                      + w3*t[58] + w4*t[59] + w5*t[60]
                      + w6*t[116] + w7*t[117] + w8*t[118];
        bf16 hh, ll; split2(a, hh, ll);
        ohp[p] = hh; olp[p] = ll;
    }
}

// ---------------- linear attention ----------------
__device__ __forceinline__ float phi_f(float t) { return expf(0.5f * (2.f*t - t*t)); }

__global__ __launch_bounds__(256)
void attn_kv_kernel(const float* __restrict__ qkv) {
    int bh = blockIdx.x; int b = bh >> 3, hd = bh & 7;
    int n0 = blockIdx.y * 392;
    __shared__ float kp_s[28*48];
    __shared__ float vv_s[28*48];
    int tid = threadIdx.x;
    int dr[9], er[9];
    #pragma unroll
    for (int r = 0; r < 9; r++) { int de = tid + 256*r; dr[r] = de/48; er[r] = de - dr[r]*48; }
    float acc[9];
    #pragma unroll
    for (int r = 0; r < 9; r++) acc[r] = 0.f;
    float ks = 0.f;
    const float* kbase = qkv + ((size_t)(b*1152 + CC   + hd*HD)) * GN + n0;
    const float* vbase = qkv + ((size_t)(b*1152 + 2*CC + hd*HD)) * GN + n0;
    for (int j0 = 0; j0 < 392; j0 += 28) {
        for (int idx = tid; idx < 48*28; idx += 256) {
            int d = idx / 28, j = idx - d*28;
            float kvl = kbase[(size_t)d*GN + j0 + j];
            kp_s[j*48 + d] = phi_f(kvl);
            vv_s[j*48 + d] = vbase[(size_t)d*GN + j0 + j];
        }
        __syncthreads();
        #pragma unroll 4
        for (int j = 0; j < 28; j++) {
            #pragma unroll
            for (int r = 0; r < 9; r++)
                acc[r] = fmaf(kp_s[j*48 + dr[r]], vv_s[j*48 + er[r]], acc[r]);
        }
        if (tid < 48) {
            float s = 0.f;
            #pragma unroll 4
            for (int j = 0; j < 28; j++) s += kp_s[j*48 + tid];
            ks += s;
        }
        __syncthreads();
    }
    #pragma unroll
    for (int r = 0; r < 9; r++) atomicAdd(&g_kv[bh*2304 + tid + 256*r], acc[r]);
    if (tid < 48) atomicAdd(&g_ksum[bh*48 + tid], ks);
}

__global__ __launch_bounds__(256)
void attn_out_kernel(const float* __restrict__ qkv,
                     bf16* __restrict__ oh, bf16* __restrict__ ol) {
    int bh = blockIdx.x; int b = bh >> 3, hd = bh & 7;
    int n0 = blockIdx.y * 392;
    __shared__ float kv_s[2304];
    __shared__ float ks_s[48];
    __shared__ float qp_s[28*49];
    __shared__ float dinv[28];
    int tid = threadIdx.x;
    for (int i = tid; i < 2304; i += 256) kv_s[i] = g_kv[bh*2304 + i];
    if (tid < 48) ks_s[tid] = g_ksum[bh*48 + tid];
    __syncthreads();
    const float* qbase = qkv + ((size_t)(b*1152 + hd*HD)) * GN + n0;
    size_t ob = ((size_t)(b*CC + hd*HD)) * GN + n0;
    for (int j0 = 0; j0 < 392; j0 += 28) {
        for (int idx = tid; idx < 48*28; idx += 256) {
            int d = idx / 28, j = idx - d*28;
            float q = qbase[(size_t)d*GN + j0 + j];
            qp_s[j*49 + d] = phi_f(q);
        }
        __syncthreads();
        if (tid < 28) {
            float s = 0.f;
            #pragma unroll
            for (int d = 0; d < 48; d++) s = fmaf(qp_s[tid*49 + d], ks_s[d], s);
            dinv[tid] = 1.f / (s + 1e-6f);
        }
        __syncthreads();
        for (int idx = tid; idx < 48*28; idx += 256) {
            int e = idx / 28, j = idx - e*28;
            float s = 0.f;
            #pragma unroll
            for (int d = 0; d < 48; d++) s = fmaf(qp_s[j*49 + d], kv_s[d*48 + e], s);
            float v = s * dinv[j];
            bf16 hh, ll; split2(v, hh, ll);
            oh[ob + (size_t)e*GN + j0 + j] = hh;
            ol[ob + (size_t)e*GN + j0 + j] = ll;
        }
        __syncthreads();
    }
}

// ---------------- LayerNorm over channels, writes bf16 hi/lo ----------------
__global__ __launch_bounds__(256)
void ln_kernel(const float* __restrict__ x2, const float* __restrict__ lw,
               const float* __restrict__ lb, bf16* __restrict__ oh, bf16* __restrict__ ol) {
    int b = blockIdx.y; int n0 = blockIdx.x * 16;
    __shared__ float s[CC*17];
    __shared__ float r1[256], r2[256];
    __shared__ float mu[16], ri[16];
    const float* base = x2 + (size_t)b * CC * GN + n0;
    int tid = threadIdx.x;
    for (int idx = tid; idx < CC*16; idx += 256) {
        int c = idx >> 4, j = idx & 15;
        s[c*17 + j] = base[(size_t)c * GN + j];
    }
    __syncthreads();
    {
        int j = tid & 15, part = tid >> 4;
        float sm = 0.f, sq = 0.f;
        for (int c = part*24; c < part*24 + 24; c++) {
            float v = s[c*17 + j]; sm += v; sq = fmaf(v, v, sq);
        }
        r1[tid] = sm; r2[tid] = sq;
    }
    __syncthreads();
    if (tid < 16) {
        float a = 0.f, q = 0.f;
        #pragma unroll
        for (int p = 0; p < 16; p++) { a += r1[p*16 + tid]; q += r2[p*16 + tid]; }
        float mean = a * (1.f/384.f);
        float var = q * (1.f/384.f) - mean*mean;
        mu[tid] = mean; ri[tid] = rsqrtf(var + 1e-5f);
    }
    __syncthreads();
    size_t ob = (size_t)b * CC * GN + n0;
    for (int idx = tid; idx < CC*16; idx += 256) {
        int c = idx >> 4, j = idx & 15;
        float v = (s[c*17 + j] - mu[j]) * ri[j] * lw[c] + lb[c];
        bf16 hh, ll; split2(v, hh, ll);
        oh[ob + (size_t)c * GN + j] = hh;
        ol[ob + (size_t)c * GN + j] = ll;
    }
}

// ---------------- launch ----------------
extern "C" void kernel_launch(void* const* d_in, const int* in_sizes, int n_in,
                              void* d_out, int out_size) {
    const float* x      = (const float*)d_in[0];
    const float* bn1_w  = (const float*)d_in[1];
    const float* bn1_b  = (const float*)d_in[2];
    const float* bn1_m  = (const float*)d_in[3];
    const float* bn1_v  = (const float*)d_in[4];
    const float* cw1    = (const float*)d_in[5];
    const float* cb1    = (const float*)d_in[6];
    const float* dw     = (const float*)d_in[7];
    const float* db     = (const float*)d_in[8];
    const float* bn2_w  = (const float*)d_in[9];
    const float* bn2_b  = (const float*)d_in[10];
    const float* bn2_m  = (const float*)d_in[11];
    const float* bn2_v  = (const float*)d_in[12];
    const float* cw2    = (const float*)d_in[13];
    const float* cb2    = (const float*)d_in[14];
    const float* qkv_w  = (const float*)d_in[15];
    const float* proj_w = (const float*)d_in[16];
    const float* proj_b = (const float*)d_in[17];
    const float* ln_w   = (const float*)d_in[18];
    const float* ln_b   = (const float*)d_in[19];
    const float* mlp_w1 = (const float*)d_in[20];
    const float* mlp_b1 = (const float*)d_in[21];
    const float* mlp_w2 = (const float*)d_in[22];
    const float* mlp_b2 = (const float*)d_in[23];

    // symbol addresses
    float *bufA, *x1, *x2, *qkvb, *w1f, *b1f, *w1t, *w2t;
    bf16 *xh,*xl,*dwh,*dwl,*x1h,*x1l,*aoh,*aol,*lnh,*lnl,*hmh,*hml;
    bf16 *w1fh,*w1fl,*cw2h,*cw2l,*qkvh,*qkvl,*projh,*projl,*w1th,*w1tl,*w2th,*w2tl;
    cudaGetSymbolAddress((void**)&bufA, g_bufA);
    cudaGetSymbolAddress((void**)&x1,   g_x1b);
    cudaGetSymbolAddress((void**)&x2,   g_x2b);
    cudaGetSymbolAddress((void**)&qkvb, g_qkvb);
    cudaGetSymbolAddress((void**)&w1f,  g_w1f);
    cudaGetSymbolAddress((void**)&b1f,  g_b1f);
    cudaGetSymbolAddress((void**)&w1t,  g_w1t);
    cudaGetSymbolAddress((void**)&w2t,  g_w2t);
    cudaGetSymbolAddress((void**)&xh,  g_xh);   cudaGetSymbolAddress((void**)&xl,  g_xl);
    cudaGetSymbolAddress((void**)&dwh, g_dwh);  cudaGetSymbolAddress((void**)&dwl, g_dwl);
    cudaGetSymbolAddress((void**)&x1h, g_x1h);  cudaGetSymbolAddress((void**)&x1l, g_x1l);
    cudaGetSymbolAddress((void**)&aoh, g_aoh);  cudaGetSymbolAddress((void**)&aol, g_aol);
    cudaGetSymbolAddress((void**)&lnh, g_lnh);  cudaGetSymbolAddress((void**)&lnl, g_lnl);
    cudaGetSymbolAddress((void**)&hmh, g_hmh);  cudaGetSymbolAddress((void**)&hml, g_hml);
    cudaGetSymbolAddress((void**)&w1fh, g_w1fh); cudaGetSymbolAddress((void**)&w1fl, g_w1fl);
    cudaGetSymbolAddress((void**)&cw2h, g_cw2h); cudaGetSymbolAddress((void**)&cw2l, g_cw2l);
    cudaGetSymbolAddress((void**)&qkvh, g_qkvh); cudaGetSymbolAddress((void**)&qkvl, g_qkvl);
    cudaGetSymbolAddress((void**)&projh, g_projh); cudaGetSymbolAddress((void**)&projl, g_projl);
    cudaGetSymbolAddress((void**)&w1th, g_w1th); cudaGetSymbolAddress((void**)&w1tl, g_w1tl);
    cudaGetSymbolAddress((void**)&w2th, g_w2th); cudaGetSymbolAddress((void**)&w2tl, g_w2tl);

    // weight prep
    fold_bn1_kernel<<<CC, 128>>>(cw1, cb1, bn1_w, bn1_b, bn1_m, bn1_v);
    fold_bn2_kernel<<<2, 192>>>(dw, db, bn2_w, bn2_b, bn2_m, bn2_v);
    transpose_kernel<<<(CC*4*CC + 255)/256, 256>>>(mlp_w1, w1t, CC, 4*CC);
    transpose_kernel<<<(CC*4*CC + 255)/256, 256>>>(mlp_w2, w2t, 4*CC, CC);
    split_kernel<<<(CC*CC + 255)/256, 256>>>(w1f, w1fh, w1fl, CC*CC);
    split_kernel<<<(CC*CC + 255)/256, 256>>>(cw2, cw2h, cw2l, CC*CC);
    split_kernel<<<(3*CC*CC + 255)/256, 256>>>(qkv_w, qkvh, qkvl, 3*CC*CC);
    split_kernel<<<(CC*CC + 255)/256, 256>>>(proj_w, projh, projl, CC*CC);
    split_kernel<<<(CC*4*CC + 255)/256, 256>>>(w1t, w1th, w1tl, CC*4*CC);
    split_kernel<<<(CC*4*CC + 255)/256, 256>>>(w2t, w2th, w2tl, CC*4*CC);
    split_kernel<<<(SZ + 255)/256, 256>>>(x, xh, xl, SZ);
    zero_kv_kernel<<<(BB*NHEADS*HD*HD + 255)/256, 256>>>();

    // conv path
    run_gemm(w1fh, w1fl, xh, xl, b1f, nullptr, bufA, nullptr, nullptr, CC, CC, 0);
    dwconv_kernel<<<BB*CC, 256>>>(bufA, dwh, dwl);
    run_gemm(cw2h, cw2l, dwh, dwl, cb2, x, x1, x1h, x1l, CC, CC, 0);   // x1 = 1x1 + x (fp32 + hi/lo)

    // linear attention
    run_gemm(qkvh, qkvl, x1h, x1l, nullptr, nullptr, qkvb, nullptr, nullptr, 3*CC, CC, 0);
    attn_kv_kernel<<<dim3(BB*NHEADS, 8), 256>>>(qkvb);
    attn_out_kernel<<<dim3(BB*NHEADS, 8), 256>>>(qkvb, aoh, aol);
    run_gemm(projh, projl, aoh, aol, proj_b, x1, x2, nullptr, nullptr, CC, CC, 0);  // x2 = proj + x1

    // LN + MLP
    ln_kernel<<<dim3(GN/16, BB), 256>>>(x2, ln_w, ln_b, lnh, lnl);
    run_gemm(w1th, w1tl, lnh, lnl, mlp_b1, nullptr, nullptr, hmh, hml, 4*CC, CC, 1);  // gelu(fc1) -> hi/lo only
    run_gemm(w2th, w2tl, hmh, hml, mlp_b2, x2, (float*)d_out, nullptr, nullptr, CC, 4*CC, 0);
}